// round 6
// baseline (speedup 1.0000x reference)
#include <cuda_runtime.h>
#include <cuda_bf16.h>

// MeanMemoryMessageReducer — segment mean + last timestamp, sorted segment_ids.
//
// SINGLE persistent kernel, exact-resident grid + software grid barrier:
//   Phase 1: grid-strided int4 transition scan -> g_bounds[s] = lower_bound(seg, s)
//   Barrier: sense-reversing generation barrier (replay-safe, deterministic)
//   Phase 2: warp-per-segment streaming mean + fused nid/last-ts epilogue,
//            persistent-strided over segments
//
// Output layout (float32): [ nids(M) | means(M*128) | last_ts(M) ]

#define DCOLS 128
#define MAX_M (1 << 20)

__device__ int g_bounds[MAX_M + 1];
__device__ unsigned g_bar_cnt = 0;
__device__ volatile unsigned g_bar_gen = 0;

__global__ __launch_bounds__(256) void fused_kernel(
    const int*   __restrict__ seg,
    const float* __restrict__ msgs,
    const int*   __restrict__ nids,
    const float* __restrict__ ts,
    float* __restrict__ out,
    int N, int M, int vec_ok)
{
    const int tid  = blockIdx.x * blockDim.x + threadIdx.x;
    const int tot  = gridDim.x * blockDim.x;

    // ---------------- Phase 1: transition scan ----------------
    const int n8 = (N + 7) >> 3;
    for (int t = tid; t < n8; t += tot) {
        const int base = t * 8;
        const int lim  = (base + 8 <= N) ? 8 : (N - base);

        int vals[8];
        if (lim == 8) {
            const int4 v0 = *reinterpret_cast<const int4*>(seg + base);
            const int4 v1 = *reinterpret_cast<const int4*>(seg + base + 4);
            vals[0] = v0.x; vals[1] = v0.y; vals[2] = v0.z; vals[3] = v0.w;
            vals[4] = v1.x; vals[5] = v1.y; vals[6] = v1.z; vals[7] = v1.w;
        } else {
            for (int j = 0; j < lim; ++j) vals[j] = seg[base + j];
        }

        int p = (base == 0) ? -1 : __ldg(seg + base - 1);

        #pragma unroll
        for (int j = 0; j < 8; ++j) {
            if (j < lim) {
                const int c = vals[j];
                for (int s = p + 1; s <= c; ++s)
                    g_bounds[s] = base + j;
                p = c;
            }
        }

        if (base + lim == N) {            // chunk owning the final element
            for (int s = p + 1; s <= M; ++s)
                g_bounds[s] = N;
        }
    }

    // ---------------- Grid barrier (all blocks resident) ----------------
    __syncthreads();
    if (threadIdx.x == 0) {
        const unsigned gen0 = g_bar_gen;          // snapshot BEFORE arriving
        __threadfence();                          // publish g_bounds writes
        const unsigned my = atomicAdd(&g_bar_cnt, 1u);
        if (my == gridDim.x - 1) {
            g_bar_cnt = 0;                        // everyone has arrived
            __threadfence();
            g_bar_gen = gen0 + 1;                 // release
        } else {
            while (g_bar_gen == gen0) __nanosleep(64);
        }
        __threadfence();                          // acquire
    }
    __syncthreads();

    // ---------------- Phase 2: warp-per-segment means ----------------
    const int gwarp  = tid >> 5;
    const int nwarps = tot >> 5;
    const int lane   = threadIdx.x & 31;

    for (int s = gwarp; s < M; s += nwarps) {
        const int start = __ldcg(&g_bounds[s]);
        const int end   = __ldcg(&g_bounds[s + 1]);
        const int cnt   = end - start;

        if (lane == 0) {
            out[s] = (float)nids[s];
            const int idx = (cnt > 0) ? (end - 1) : 0;   // ref clips empty to 0
            out[(size_t)M * (DCOLS + 1) + s] = ts[idx];
        }

        // Row = 128 floats = 32 float4; lane l owns columns [4l, 4l+4).
        const float4* p = reinterpret_cast<const float4*>(msgs)
                          + (size_t)start * 32 + lane;

        float4 acc = make_float4(0.f, 0.f, 0.f, 0.f);
        int n = cnt;
        while (n >= 4) {                  // 4 independent LDG.128 in flight
            float4 a = __ldcs(p);
            float4 b = __ldcs(p + 32);
            float4 c = __ldcs(p + 64);
            float4 d = __ldcs(p + 96);
            acc.x += (a.x + b.x) + (c.x + d.x);
            acc.y += (a.y + b.y) + (c.y + d.y);
            acc.z += (a.z + b.z) + (c.z + d.z);
            acc.w += (a.w + b.w) + (c.w + d.w);
            p += 128;
            n -= 4;
        }
        while (n > 0) {
            float4 a = __ldcs(p);
            acc.x += a.x; acc.y += a.y; acc.z += a.z; acc.w += a.w;
            p += 32;
            n -= 1;
        }

        const float inv = 1.0f / fmaxf((float)cnt, 1.0f);
        acc.x *= inv; acc.y *= inv; acc.z *= inv; acc.w *= inv;

        float* ob = out + (size_t)M + (size_t)s * DCOLS + lane * 4;
        if (vec_ok) {
            __stcs(reinterpret_cast<float4*>(ob), acc);
        } else {
            ob[0] = acc.x; ob[1] = acc.y; ob[2] = acc.z; ob[3] = acc.w;
        }
    }
}

extern "C" void kernel_launch(void* const* d_in, const int* in_sizes, int n_in,
                              void* d_out, int out_size)
{
    const int*   nids = (const int*)d_in[0];
    const float* msgs = (const float*)d_in[1];
    const float* ts   = (const float*)d_in[2];
    const int*   seg  = (const int*)d_in[3];
    float* out = (float*)d_out;

    const int M = in_sizes[0];
    const int N = in_sizes[2];
    const int vec_ok = ((M & 3) == 0) ? 1 : 0;

    // Exact-resident grid: spin barrier is safe only if every block is resident.
    int dev = 0, sms = 0, bpm = 0;
    cudaGetDevice(&dev);
    cudaDeviceGetAttribute(&sms, cudaDevAttrMultiProcessorCount, dev);
    cudaOccupancyMaxActiveBlocksPerMultiprocessor(&bpm, fused_kernel, 256, 0);
    if (sms <= 0) sms = 148;
    if (bpm <= 0) bpm = 1;
    const int grid = sms * bpm;

    fused_kernel<<<grid, 256>>>(seg, msgs, nids, ts, out, N, M, vec_ok);
}

// round 7
// speedup vs baseline: 1.0793x; 1.0793x over previous
#include <cuda_runtime.h>
#include <cuda_bf16.h>

// MeanMemoryMessageReducer — segment mean + last timestamp, sorted segment_ids.
//
// 2-kernel pipeline (R4 structure, reworked mean inner loop):
//   K1 bounds_scan_v4 : int4 transition scan -> bounds[s] = lower_bound(seg, s)
//   K2 mean_kernel    : warp-per-segment; MLP-8 main batches + predicated MLP-3
//                       tail (no scalar remainder loop); fused epilogue
//
// Output layout (float32): [ nids(M) | means(M*128) | last_ts(M) ]

#define DCOLS 128
#define MAX_M (1 << 20)

__device__ int g_bounds[MAX_M + 1];

__global__ __launch_bounds__(256) void bounds_scan_v4(
    const int* __restrict__ seg, int N, int M)
{
    const int i = blockIdx.x * blockDim.x + threadIdx.x;
    const int base = i * 4;
    if (base >= N) return;

    int vals[4];
    if (base + 3 < N) {
        const int4 v = *reinterpret_cast<const int4*>(seg + base);
        vals[0] = v.x; vals[1] = v.y; vals[2] = v.z; vals[3] = v.w;
    } else {
        #pragma unroll
        for (int j = 0; j < 4; ++j)
            vals[j] = (base + j < N) ? seg[base + j] : vals[j > 0 ? j - 1 : 0];
    }

    int p = (base == 0) ? -1 : seg[base - 1];

    const int lim = (base + 4 <= N) ? 4 : (N - base);
    #pragma unroll
    for (int j = 0; j < 4; ++j) {
        if (j < lim) {
            const int c = vals[j];
            for (int s = p + 1; s <= c; ++s)
                g_bounds[s] = base + j;
            p = c;
        }
    }

    if (base + lim == N) {
        for (int s = p + 1; s <= M; ++s)
            g_bounds[s] = N;
    }
}

__global__ __launch_bounds__(256) void mean_kernel(
    const float* __restrict__ msgs,
    const int*   __restrict__ nids,
    const float* __restrict__ ts,
    float* __restrict__ out,
    int M, int vec_ok)
{
    const int warp = (int)((blockIdx.x * blockDim.x + threadIdx.x) >> 5);
    const int lane = threadIdx.x & 31;
    if (warp >= M) return;

    const int start = __ldg(&g_bounds[warp]);
    const int end   = __ldg(&g_bounds[warp + 1]);
    const int cnt   = end - start;

    // Fused epilogue: nid cast + last timestamp (ref clips empty-seg idx to 0)
    if (lane == 0) {
        out[warp] = (float)nids[warp];
        const int idx = (cnt > 0) ? (end - 1) : 0;
        out[(size_t)M * (DCOLS + 1) + warp] = ts[idx];
    }

    float4 acc = make_float4(0.f, 0.f, 0.f, 0.f);

    if (cnt > 0) {
        // Row = 128 floats = 32 float4; lane l owns columns [4l, 4l+4).
        const float4* p = reinterpret_cast<const float4*>(msgs)
                          + (size_t)start * 32 + lane;
        int n = cnt;

        // MLP-8 main batch: 8 independent LDG.128 in flight
        while (n >= 8) {
            float4 a0 = __ldcs(p);
            float4 a1 = __ldcs(p + 32);
            float4 a2 = __ldcs(p + 64);
            float4 a3 = __ldcs(p + 96);
            float4 a4 = __ldcs(p + 128);
            float4 a5 = __ldcs(p + 160);
            float4 a6 = __ldcs(p + 192);
            float4 a7 = __ldcs(p + 224);
            acc.x += ((a0.x + a1.x) + (a2.x + a3.x)) + ((a4.x + a5.x) + (a6.x + a7.x));
            acc.y += ((a0.y + a1.y) + (a2.y + a3.y)) + ((a4.y + a5.y) + (a6.y + a7.y));
            acc.z += ((a0.z + a1.z) + (a2.z + a3.z)) + ((a4.z + a5.z) + (a6.z + a7.z));
            acc.w += ((a0.w + a1.w) + (a2.w + a3.w)) + ((a4.w + a5.w) + (a6.w + a7.w));
            p += 256;
            n -= 8;
        }

        if (n >= 4) {
            float4 a0 = __ldcs(p);
            float4 a1 = __ldcs(p + 32);
            float4 a2 = __ldcs(p + 64);
            float4 a3 = __ldcs(p + 96);
            acc.x += (a0.x + a1.x) + (a2.x + a3.x);
            acc.y += (a0.y + a1.y) + (a2.y + a3.y);
            acc.z += (a0.z + a1.z) + (a2.z + a3.z);
            acc.w += (a0.w + a1.w) + (a2.w + a3.w);
            p += 128;
            n -= 4;
        }

        if (n > 0) {
            // Predicated MLP-3 tail: clamped addresses stay valid (rows already
            // in the segment), masked-out rows contribute 0 via FFMA scale.
            const float m1 = (n > 1) ? 1.0f : 0.0f;
            const float m2 = (n > 2) ? 1.0f : 0.0f;
            float4 a0 = __ldcs(p);
            float4 a1 = __ldcs(p + ((n > 1) ? 32 : 0));
            float4 a2 = __ldcs(p + ((n > 2) ? 64 : 0));
            acc.x += a0.x + m1 * a1.x + m2 * a2.x;
            acc.y += a0.y + m1 * a1.y + m2 * a2.y;
            acc.z += a0.z + m1 * a1.z + m2 * a2.z;
            acc.w += a0.w + m1 * a1.w + m2 * a2.w;
        }
    }

    const float inv = 1.0f / fmaxf((float)cnt, 1.0f);
    acc.x *= inv; acc.y *= inv; acc.z *= inv; acc.w *= inv;

    float* ob = out + (size_t)M + (size_t)warp * DCOLS + lane * 4;
    if (vec_ok) {
        __stcs(reinterpret_cast<float4*>(ob), acc);
    } else {
        ob[0] = acc.x; ob[1] = acc.y; ob[2] = acc.z; ob[3] = acc.w;
    }
}

extern "C" void kernel_launch(void* const* d_in, const int* in_sizes, int n_in,
                              void* d_out, int out_size)
{
    const int*   nids = (const int*)d_in[0];
    const float* msgs = (const float*)d_in[1];
    const float* ts   = (const float*)d_in[2];
    const int*   seg  = (const int*)d_in[3];
    float* out = (float*)d_out;

    const int M = in_sizes[0];
    const int N = in_sizes[2];
    const int vec_ok = ((M & 3) == 0) ? 1 : 0;   // out+M 16B-aligned

    const int n4 = (N + 3) / 4;
    bounds_scan_v4<<<(n4 + 255) / 256, 256>>>(seg, N, M);

    const long long threads = (long long)M * 32;
    mean_kernel<<<(unsigned)((threads + 255) / 256), 256>>>(
        msgs, nids, ts, out, M, vec_ok);
}

// round 8
// speedup vs baseline: 1.0853x; 1.0055x over previous
#include <cuda_runtime.h>
#include <cuda_bf16.h>

// MeanMemoryMessageReducer — segment mean + last timestamp, sorted segment_ids.
//
// 2-kernel pipeline:
//   K1 bounds_scan_v4 : int4 transition scan -> bounds[s] = lower_bound(seg, s)
//                       PLUS fused epilogue: nid cast and last-timestamp are
//                       emitted at the transitions (segment a ends at i-1;
//                       empty segments get ts[0] per the reference's clip-to-0)
//   K2 mean_kernel    : pure streaming warp-per-segment mean; MLP-4 main loop,
//                       predicated MLP-3 tail, minimal registers
//
// Output layout (float32): [ nids(M) | means(M*128) | last_ts(M) ]

#define DCOLS 128
#define MAX_M (1 << 20)

__device__ int g_bounds[MAX_M + 1];

__global__ __launch_bounds__(256) void bounds_scan_v4(
    const int*   __restrict__ seg,
    const int*   __restrict__ nids,
    const float* __restrict__ ts,
    float* __restrict__ out,
    int N, int M)
{
    const int i = blockIdx.x * blockDim.x + threadIdx.x;

    // nid cast: coalesced, one element per thread (grid covers M since M < N/4+pad)
    if (i < M) out[i] = (float)nids[i];

    const int base = i * 4;
    if (base >= N) return;

    float* last_ts = out + (size_t)M * (DCOLS + 1);
    const float ts0 = ts[0];                  // empty segments -> ts[0]

    int vals[4];
    if (base + 3 < N) {
        const int4 v = *reinterpret_cast<const int4*>(seg + base);
        vals[0] = v.x; vals[1] = v.y; vals[2] = v.z; vals[3] = v.w;
    } else {
        #pragma unroll
        for (int j = 0; j < 4; ++j)
            vals[j] = (base + j < N) ? seg[base + j] : vals[j > 0 ? j - 1 : 0];
    }

    int p = (base == 0) ? -1 : seg[base - 1];

    const int lim = (base + 4 <= N) ? 4 : (N - base);
    #pragma unroll
    for (int j = 0; j < 4; ++j) {
        if (j < lim) {
            const int c   = vals[j];
            const int idx = base + j;
            if (c > p) {
                // segment p ends at idx-1
                if (p >= 0) last_ts[p] = ts[idx - 1];
                // segments (p, c) are empty
                for (int s = p + 1; s < c; ++s) last_ts[s] = ts0;
                // bounds for s in (p, c]
                for (int s = p + 1; s <= c; ++s) g_bounds[s] = idx;
            }
            p = c;
        }
    }

    if (base + lim == N) {                    // thread owning the final element
        last_ts[p] = ts[N - 1];               // last segment ends at N-1
        for (int s = p + 1; s < M; ++s) last_ts[s] = ts0;
        for (int s = p + 1; s <= M; ++s) g_bounds[s] = N;
    }
}

__global__ __launch_bounds__(256) void mean_kernel(
    const float* __restrict__ msgs,
    float* __restrict__ out_means,            // out + M
    int M, int vec_ok)
{
    const int warp = (int)((blockIdx.x * blockDim.x + threadIdx.x) >> 5);
    const int lane = threadIdx.x & 31;
    if (warp >= M) return;

    const int start = __ldg(&g_bounds[warp]);
    const int end   = __ldg(&g_bounds[warp + 1]);
    const int cnt   = end - start;

    float4 acc = make_float4(0.f, 0.f, 0.f, 0.f);

    if (cnt > 0) {
        // Row = 128 floats = 32 float4; lane l owns columns [4l, 4l+4).
        const float4* p = reinterpret_cast<const float4*>(msgs)
                          + (size_t)start * 32 + lane;
        int n = cnt;

        while (n >= 4) {                      // 4 independent LDG.128 in flight
            float4 a = __ldcs(p);
            float4 b = __ldcs(p + 32);
            float4 c = __ldcs(p + 64);
            float4 d = __ldcs(p + 96);
            acc.x += (a.x + b.x) + (c.x + d.x);
            acc.y += (a.y + b.y) + (c.y + d.y);
            acc.z += (a.z + b.z) + (c.z + d.z);
            acc.w += (a.w + b.w) + (c.w + d.w);
            p += 128;
            n -= 4;
        }

        if (n > 0) {
            // Predicated MLP-3 tail: clamped offsets stay inside the segment,
            // masked rows contribute 0 via FFMA scale.
            const float m1 = (n > 1) ? 1.0f : 0.0f;
            const float m2 = (n > 2) ? 1.0f : 0.0f;
            float4 a = __ldcs(p);
            float4 b = __ldcs(p + ((n > 1) ? 32 : 0));
            float4 c = __ldcs(p + ((n > 2) ? 64 : 0));
            acc.x += a.x + m1 * b.x + m2 * c.x;
            acc.y += a.y + m1 * b.y + m2 * c.y;
            acc.z += a.z + m1 * b.z + m2 * c.z;
            acc.w += a.w + m1 * b.w + m2 * c.w;
        }
    }

    const float inv = 1.0f / fmaxf((float)cnt, 1.0f);
    acc.x *= inv; acc.y *= inv; acc.z *= inv; acc.w *= inv;

    float* ob = out_means + (size_t)warp * DCOLS + lane * 4;
    if (vec_ok) {
        __stcs(reinterpret_cast<float4*>(ob), acc);
    } else {
        ob[0] = acc.x; ob[1] = acc.y; ob[2] = acc.z; ob[3] = acc.w;
    }
}

extern "C" void kernel_launch(void* const* d_in, const int* in_sizes, int n_in,
                              void* d_out, int out_size)
{
    const int*   nids = (const int*)d_in[0];
    const float* msgs = (const float*)d_in[1];
    const float* ts   = (const float*)d_in[2];
    const int*   seg  = (const int*)d_in[3];
    float* out = (float*)d_out;

    const int M = in_sizes[0];
    const int N = in_sizes[2];
    const int vec_ok = ((M & 3) == 0) ? 1 : 0;   // out+M 16B-aligned

    const int n4 = (N + 3) / 4;
    const int k1_threads = (n4 > M) ? n4 : M;    // cover both scan and nid cast
    bounds_scan_v4<<<(k1_threads + 255) / 256, 256>>>(seg, nids, ts, out, N, M);

    const long long threads = (long long)M * 32;
    mean_kernel<<<(unsigned)((threads + 255) / 256), 256>>>(
        msgs, out + M, M, vec_ok);
}

// round 9
// speedup vs baseline: 1.0909x; 1.0052x over previous
#include <cuda_runtime.h>
#include <cuda_bf16.h>

// MeanMemoryMessageReducer — segment mean + last timestamp, sorted segment_ids.
//
// 2-kernel pipeline (best-of-both recombination):
//   K1 bounds_scan_v4 : LIGHT int4 transition scan -> bounds only
//   K2 mean_kernel    : warp-per-segment; MLP-4 main + predicated MLP-3 tail;
//                       lane-0 epilogue (nid cast + last-timestamp gather)
//
// Output layout (float32): [ nids(M) | means(M*128) | last_ts(M) ]

#define DCOLS 128
#define MAX_M (1 << 20)

__device__ int g_bounds[MAX_M + 1];

__global__ __launch_bounds__(256) void bounds_scan_v4(
    const int* __restrict__ seg, int N, int M)
{
    const int i = blockIdx.x * blockDim.x + threadIdx.x;
    const int base = i * 4;
    if (base >= N) return;

    int vals[4];
    if (base + 3 < N) {
        const int4 v = *reinterpret_cast<const int4*>(seg + base);
        vals[0] = v.x; vals[1] = v.y; vals[2] = v.z; vals[3] = v.w;
    } else {
        #pragma unroll
        for (int j = 0; j < 4; ++j)
            vals[j] = (base + j < N) ? seg[base + j] : vals[j > 0 ? j - 1 : 0];
    }

    int p = (base == 0) ? -1 : seg[base - 1];

    const int lim = (base + 4 <= N) ? 4 : (N - base);
    #pragma unroll
    for (int j = 0; j < 4; ++j) {
        if (j < lim) {
            const int c = vals[j];
            for (int s = p + 1; s <= c; ++s)
                g_bounds[s] = base + j;
            p = c;
        }
    }

    if (base + lim == N) {
        for (int s = p + 1; s <= M; ++s)
            g_bounds[s] = N;
    }
}

__global__ __launch_bounds__(256) void mean_kernel(
    const float* __restrict__ msgs,
    const int*   __restrict__ nids,
    const float* __restrict__ ts,
    float* __restrict__ out,
    int M, int vec_ok)
{
    const int warp = (int)((blockIdx.x * blockDim.x + threadIdx.x) >> 5);
    const int lane = threadIdx.x & 31;
    if (warp >= M) return;

    const int start = __ldg(&g_bounds[warp]);
    const int end   = __ldg(&g_bounds[warp + 1]);
    const int cnt   = end - start;

    // Lane-0 epilogue: nid cast + last timestamp (ref clips empty-seg idx to 0)
    if (lane == 0) {
        out[warp] = (float)nids[warp];
        const int idx = (cnt > 0) ? (end - 1) : 0;
        out[(size_t)M * (DCOLS + 1) + warp] = ts[idx];
    }

    float4 acc = make_float4(0.f, 0.f, 0.f, 0.f);

    if (cnt > 0) {
        // Row = 128 floats = 32 float4; lane l owns columns [4l, 4l+4).
        const float4* p = reinterpret_cast<const float4*>(msgs)
                          + (size_t)start * 32 + lane;
        int n = cnt;

        while (n >= 4) {                      // 4 independent LDG.128 in flight
            float4 a = __ldcs(p);
            float4 b = __ldcs(p + 32);
            float4 c = __ldcs(p + 64);
            float4 d = __ldcs(p + 96);
            acc.x += (a.x + b.x) + (c.x + d.x);
            acc.y += (a.y + b.y) + (c.y + d.y);
            acc.z += (a.z + b.z) + (c.z + d.z);
            acc.w += (a.w + b.w) + (c.w + d.w);
            p += 128;
            n -= 4;
        }

        if (n > 0) {
            // Predicated MLP-3 tail: clamped offsets stay inside the segment,
            // masked rows contribute 0 via FFMA scale.
            const float m1 = (n > 1) ? 1.0f : 0.0f;
            const float m2 = (n > 2) ? 1.0f : 0.0f;
            float4 a = __ldcs(p);
            float4 b = __ldcs(p + ((n > 1) ? 32 : 0));
            float4 c = __ldcs(p + ((n > 2) ? 64 : 0));
            acc.x += a.x + m1 * b.x + m2 * c.x;
            acc.y += a.y + m1 * b.y + m2 * c.y;
            acc.z += a.z + m1 * b.z + m2 * c.z;
            acc.w += a.w + m1 * b.w + m2 * c.w;
        }
    }

    const float inv = 1.0f / fmaxf((float)cnt, 1.0f);
    acc.x *= inv; acc.y *= inv; acc.z *= inv; acc.w *= inv;

    float* ob = out + (size_t)M + (size_t)warp * DCOLS + lane * 4;
    if (vec_ok) {
        __stcs(reinterpret_cast<float4*>(ob), acc);
    } else {
        ob[0] = acc.x; ob[1] = acc.y; ob[2] = acc.z; ob[3] = acc.w;
    }
}

extern "C" void kernel_launch(void* const* d_in, const int* in_sizes, int n_in,
                              void* d_out, int out_size)
{
    const int*   nids = (const int*)d_in[0];
    const float* msgs = (const float*)d_in[1];
    const float* ts   = (const float*)d_in[2];
    const int*   seg  = (const int*)d_in[3];
    float* out = (float*)d_out;

    const int M = in_sizes[0];
    const int N = in_sizes[2];
    const int vec_ok = ((M & 3) == 0) ? 1 : 0;   // out+M 16B-aligned

    const int n4 = (N + 3) / 4;
    bounds_scan_v4<<<(n4 + 255) / 256, 256>>>(seg, N, M);

    const long long threads = (long long)M * 32;
    mean_kernel<<<(unsigned)((threads + 255) / 256), 256>>>(
        msgs, nids, ts, out, M, vec_ok);
}